// round 6
// baseline (speedup 1.0000x reference)
#include <cuda_runtime.h>
#include <cuda_bf16.h>
#include <cstdint>

typedef unsigned long long ull;

// ---- packed f32x2 helpers (issue-slot saver) ------------------------------
__device__ __forceinline__ ull pk2(float lo, float hi) {
    ull r; asm("mov.b64 %0, {%1, %2};" : "=l"(r) : "f"(lo), "f"(hi)); return r;
}
__device__ __forceinline__ ull bc2(float v) { return pk2(v, v); }
__device__ __forceinline__ void ffma2(ull& d, ull a, ull b) {
    asm("fma.rn.f32x2 %0, %1, %2, %3;" : "=l"(d) : "l"(a), "l"(b), "l"(d));
}
__device__ __forceinline__ float2 up2(ull v) {
    float2 f; asm("mov.b64 {%0, %1}, %2;" : "=f"(f.x), "=f"(f.y) : "l"(v)); return f;
}

// ---- mma.sync m16n8k16 bf16 (sm_80+ PTX, valid on compute_103) ------------
__device__ __forceinline__ void mma16816(float* d, const uint32_t* a, uint32_t b0, uint32_t b1) {
    asm volatile(
        "mma.sync.aligned.m16n8k16.row.col.f32.bf16.bf16.f32 "
        "{%0,%1,%2,%3}, {%4,%5,%6,%7}, {%8,%9}, {%0,%1,%2,%3};"
        : "+f"(d[0]), "+f"(d[1]), "+f"(d[2]), "+f"(d[3])
        : "r"(a[0]), "r"(a[1]), "r"(a[2]), "r"(a[3]), "r"(b0), "r"(b1));
}
__device__ __forceinline__ uint32_t pkbf(__nv_bfloat16 lo, __nv_bfloat16 hi) {
    return ((uint32_t)__bfloat16_as_ushort(hi) << 16) | __bfloat16_as_ushort(lo);
}
// split v0,v1 (v0 -> low half = first element) into bf16 hi/lo packed regs
__device__ __forceinline__ void split2(float v0, float v1, uint32_t& h, uint32_t& l) {
    __nv_bfloat16 h0 = __float2bfloat16(v0), h1 = __float2bfloat16(v1);
    float r0 = v0 - __bfloat162float(h0), r1 = v1 - __bfloat162float(h1);
    h = pkbf(h0, h1);
    l = pkbf(__float2bfloat16(r0), __float2bfloat16(r1));
}

// ---------------- scratch buffers (static device globals; no allocation) ----
__device__ float g_buf1[64u*32u*132u*132u]; // conv1 out
__device__ float g_buf2[64u*32u*66u*66u];   // region+pool+bn2 out
__device__ float g_buf3[64u*16u*59u*59u];   // conv2 out
__device__ float g_buf4[64u*16u*52u*52u];   // conv3 out
__device__ float g_buf5[64u*16u*24u*24u];   // conv4 out
__device__ float g_buf6[64u*16u*20u*20u];   // conv5 out (fc input)
__device__ float g_fc1o[64u*4096u];
__device__ float g_fc2o[64u*2048u];
// conv1 weights, fragment layout: [pass(hi/lo)][step 24][oc 32][kk 16] ushort
__device__ __align__(16) unsigned short g_c1w[2*24*32*16];

// ===========================================================================
// conv1 weight prep: w (32,3,11,11) -> bf16 hi/lo, K padded to 384 (zeros).
// ===========================================================================
__global__ void conv1_bprep(const float* __restrict__ w) {
    int i = blockIdx.x * 256 + threadIdx.x;   // 32*384
    if (i >= 12288) return;
    int oc = i / 384, k = i % 384;
    float v = (k < 363) ? w[oc*363 + k] : 0.f;
    __nv_bfloat16 h = __float2bfloat16(v);
    __nv_bfloat16 l = __float2bfloat16(v - __bfloat162float(h));
    int step = k >> 4, kk = k & 15;
    int idx = (step*32 + oc)*16 + kk;
    g_c1w[idx]         = __bfloat16_as_ushort(h);
    g_c1w[12288 + idx] = __bfloat16_as_ushort(l);
}

// ===========================================================================
// conv1 via mma.sync: implicit GEMM D[128px,32oc] = A[128,384] @ B[32,384]^T
// Split-bf16 3-pass. Block: 256 thr = 8 warps x 16px. 24 k-steps.
// ===========================================================================
__global__ void __launch_bounds__(256, 2)
conv1_mma(const float* __restrict__ x,
          const float* __restrict__ bias,
          float* __restrict__ out) {
    extern __shared__ __align__(16) char dsm[];
    unsigned short* s_w = (unsigned short*)dsm;          // 49152 B
    float* s_x  = (float*)(dsm + 49152);                 // 5112 f = 20448 B
    int*   s_of = (int*)(dsm + 49152 + 20448);           // 384 ints

    const int tid  = threadIdx.x;
    const int warp = tid >> 5;
    const int lane = tid & 31;
    const int g    = lane >> 2;        // groupID
    const int tg   = lane & 3;         // threadID in group
    const int b    = blockIdx.y;
    const int p0   = blockIdx.x * 128;
    const int y0   = p0 / 132;

    // stage offset table
    for (int i = tid; i < 384; i += 256) {
        int o = 0;
        if (i < 363) {
            int c = i / 121, r = i % 121;
            o = (c*12 + r/11)*142 + (r % 11);
        }
        s_of[i] = o;
    }
    // stage weights (48KB = 3072 float4)
    {
        const float4* gw = (const float4*)g_c1w;
        float4* sw4 = (float4*)s_w;
        for (int i = tid; i < 3072; i += 256) sw4[i] = gw[i];
    }
    // stage input rows y0..y0+11, 3ch x 142 (row-clamped)
    for (int i = tid; i < 5112; i += 256) {
        int c = i / 1704, r = (i / 142) % 12, col = i % 142;
        int ry = y0 + r; if (ry > 141) ry = 141;
        s_x[i] = x[((b*3 + c)*142 + ry)*142 + col];
    }
    __syncthreads();

    // A-row bases for this thread (rows g and g+8 of the warp's 16-px tile)
    int pxw = p0 + warp*16;
    int pr0 = pxw + g;      if (pr0 > 17423) pr0 = 17423;
    int pr1 = pxw + g + 8;  if (pr1 > 17423) pr1 = 17423;
    const int base0 = (pr0/132 - y0)*142 + pr0 % 132;
    const int base1 = (pr1/132 - y0)*142 + pr1 % 132;

    float acc[4][4];
#pragma unroll
    for (int nt = 0; nt < 4; nt++)
#pragma unroll
        for (int r = 0; r < 4; r++) acc[nt][r] = 0.f;

#pragma unroll 1
    for (int step = 0; step < 24; step++) {
        const int kb = step*16 + tg*2;
        int2 oA = *(const int2*)&s_of[kb];        // ofs[kb], ofs[kb+1]
        int2 oB = *(const int2*)&s_of[kb + 8];

        uint32_t ah[4], al[4];
        split2(s_x[base0 + oA.x], s_x[base0 + oA.y], ah[0], al[0]);
        split2(s_x[base1 + oA.x], s_x[base1 + oA.y], ah[1], al[1]);
        split2(s_x[base0 + oB.x], s_x[base0 + oB.y], ah[2], al[2]);
        split2(s_x[base1 + oB.x], s_x[base1 + oB.y], ah[3], al[3]);

        const unsigned short* wst = s_w + (step*32 + g)*16 + tg*2;
#pragma unroll
        for (int nt = 0; nt < 4; nt++) {
            const unsigned short* wp = wst + nt*128;   // +8 oc = 8*16 ushort
            uint32_t bh0 = *(const uint32_t*)(wp);
            uint32_t bh1 = *(const uint32_t*)(wp + 8);
            uint32_t bl0 = *(const uint32_t*)(wp + 12288);
            uint32_t bl1 = *(const uint32_t*)(wp + 12296);
            mma16816(acc[nt], ah, bh0, bh1);
            mma16816(acc[nt], ah, bl0, bl1);
            mma16816(acc[nt], al, bh0, bh1);
        }
    }

    // store: c0,c1 -> row g (oc tg*2, tg*2+1); c2,c3 -> row g+8
    const int sr0 = pxw + g, sr1 = pxw + g + 8;
#pragma unroll
    for (int nt = 0; nt < 4; nt++) {
        int oc = nt*8 + tg*2;
        float bs0 = __ldg(&bias[oc]), bs1 = __ldg(&bias[oc+1]);
        float* op0 = &out[((long)b*32 + oc)*17424];
        float* op1 = op0 + 17424;
        if (sr0 < 17424) {
            op0[sr0] = acc[nt][0] + bs0;
            op1[sr0] = acc[nt][1] + bs1;
        }
        if (sr1 < 17424) {
            op0[sr1] = acc[nt][2] + bs0;
            op1[sr1] = acc[nt][3] + bs1;
        }
    }
}

// ===========================================================================
// region layer fused (round-4, passing)
// ===========================================================================
__global__ void __launch_bounds__(288)
region_kernel(const float* __restrict__ xin,
              const float* __restrict__ rg_g, const float* __restrict__ rg_b,
              const float* __restrict__ rg_m, const float* __restrict__ rg_v,
              const float* __restrict__ rg_w, const float* __restrict__ rg_cb,
              const float* __restrict__ bn2_g, const float* __restrict__ bn2_b,
              const float* __restrict__ bn2_m, const float* __restrict__ bn2_v,
              float* __restrict__ out) {
    __shared__ float smem[11008];
    __shared__ float s_scale[32], s_shift[32], s_cb[32], s_a2[32], s_b2[32];

    const int tile = blockIdx.x;
    const int b    = blockIdx.y;
    const int ti = tile >> 3, tj = tile & 7;
    const int th = (ti < 7) ? 18 : 6, tw = (tj < 7) ? 18 : 6;
    const int gy0 = ti * 18, gx0 = tj * 18;
    const int tid = threadIdx.x;

    if (tid < 32) {
        int p = tile*32 + tid;
        float a = rg_g[p] * rsqrtf(rg_v[p] + 1e-5f);
        s_scale[tid] = a;
        s_shift[tid] = rg_b[p] - rg_m[p]*a;
        s_cb[tid]    = rg_cb[p];
    } else if (tid < 64) {
        int c = tid - 32;
        float a2 = bn2_g[c] * rsqrtf(bn2_v[c] + 1e-5f);
        s_a2[c] = a2;
        s_b2[c] = bn2_b[c] - bn2_m[c]*a2;
    }

    const int hp = th + 2, wp = tw + 2;
    const int npx = tw / 6, npy = th / 6;
    const int pos = tid >> 5;
    const int oc  = tid & 31;
    const bool active = pos < npx * npy;
    const int prow = (pos / npx) * 6;
    const int pcol = (pos % npx) * 6;

    float* s_in = smem;
    float* s_w  = smem + 6400;

    ull acc2[6][3];
#pragma unroll
    for (int i = 0; i < 6; i++)
#pragma unroll
        for (int j = 0; j < 3; j++) acc2[i][j] = 0ull;

    for (int chunk = 0; chunk < 2; chunk++) {
        const int ic0 = chunk * 16;
        __syncthreads();
        const int nin = 16 * hp * wp;
        for (int i = tid; i < nin; i += 288) {
            int icl = i / (hp*wp);
            int r = i % (hp*wp);
            int y = r / wp, xx = r % wp;
            float v = 0.f;
            if (y > 0 && y < hp-1 && xx > 0 && xx < wp-1) {
                float raw = xin[(((long)b*32 + ic0 + icl)*132 + gy0 + y - 1)*132 + gx0 + xx - 1];
                v = fmaxf(s_scale[ic0+icl]*raw + s_shift[ic0+icl], 0.f);
            }
            s_in[i] = v;
        }
        for (int i = tid; i < 32*16*9; i += 288) {
            int o = i / 144;
            int r = i % 144;
            s_w[i] = rg_w[(long)tile*9216 + o*288 + ic0*9 + r];
        }
        __syncthreads();

        if (active) {
            for (int icl = 0; icl < 16; icl++) {
                ull wr2[9];
#pragma unroll
                for (int k = 0; k < 9; k++) wr2[k] = bc2(s_w[oc*144 + icl*9 + k]);
                const float* ib = &s_in[icl*hp*wp + prow*wp + pcol];
#pragma unroll
                for (int r = 0; r < 8; r++) {
                    float iv[8];
#pragma unroll
                    for (int j = 0; j < 8; j++) iv[j] = ib[r*wp + j];
                    ull p[7];
#pragma unroll
                    for (int i = 0; i < 7; i++) p[i] = pk2(iv[i], iv[i+1]);
#pragma unroll
                    for (int ky = 0; ky < 3; ky++) {
                        int orow = r - ky;
                        if (orow >= 0 && orow < 6) {
#pragma unroll
                            for (int kx = 0; kx < 3; kx++) {
                                ull w2 = wr2[ky*3 + kx];
                                ffma2(acc2[orow][0], p[kx    ], w2);
                                ffma2(acc2[orow][1], p[kx + 2], w2);
                                ffma2(acc2[orow][2], p[kx + 4], w2);
                            }
                        }
                    }
                }
            }
        }
    }

    __syncthreads();
    if (active) {
        const float cb = s_cb[oc];
#pragma unroll
        for (int i = 0; i < 6; i++)
#pragma unroll
            for (int jp = 0; jp < 3; jp++) {
                float2 f = up2(acc2[i][jp]);
                smem[(oc*th + prow + i)*tw + pcol + 2*jp    ] = f.x + cb;
                smem[(oc*th + prow + i)*tw + pcol + 2*jp + 1] = f.y + cb;
            }
    }
    __syncthreads();

    const int ph = th / 2, pw = tw / 2;
    const int npool = 32 * ph * pw;
    for (int i = tid; i < npool; i += 288) {
        int c = i / (ph*pw);
        int r = i % (ph*pw);
        int py = r / pw, px = r % pw;
        const float* cp = &smem[(c*th + 2*py)*tw + 2*px];
        const float* rp = &xin[(((long)b*32 + c)*132 + gy0 + 2*py)*132 + gx0 + 2*px];
        float v00 = fmaxf(cp[0]    + rp[0],     0.f);
        float v01 = fmaxf(cp[1]    + rp[1],     0.f);
        float v10 = fmaxf(cp[tw]   + rp[132],   0.f);
        float v11 = fmaxf(cp[tw+1] + rp[133],   0.f);
        float m = fmaxf(fmaxf(v00, v01), fmaxf(v10, v11));
        out[(((long)b*32 + c)*66 + ti*9 + py)*66 + tj*9 + px] = s_a2[c]*m + s_b2[c];
    }
}

// ===========================================================================
// conv2 / conv3 (round-4, passing)
// ===========================================================================
template<int CIN, int HIN, int WIN, int HOUT, int WOUT>
__global__ void __launch_bounds__(256, 2)
conv8x8_relu_kernel(const float* __restrict__ in,
                    const float* __restrict__ w,
                    const float* __restrict__ bias,
                    float* __restrict__ out) {
    __shared__ float  s_in[8*15*40];
    __shared__ float2 s_w2[8*8*64];
    const int x0 = blockIdx.x * 32, y0 = blockIdx.y * 8;
    const int b = blockIdx.z;
    const int tid = threadIdx.x;
    const int pr  = tid >> 5;
    const int s   = tid & 31;
    const int row = s >> 2;
    const int cs  = (s & 3) * 8;

    ull acc2[8];
#pragma unroll
    for (int j = 0; j < 8; j++) acc2[j] = 0ull;

    for (int chunk = 0; chunk < CIN/8; chunk++) {
        const int ic0 = chunk * 8;
        __syncthreads();
        for (int i = tid; i < 8*15*40; i += 256) {
            int icl = i / 600;
            int r = (i / 40) % 15, c = i % 40;
            int iy = y0 + r, ix = x0 + c;
            float v = 0.f;
            if (c < 39 && iy < HIN && ix < WIN)
                v = in[(((long)b*CIN + ic0 + icl)*HIN + iy)*WIN + ix];
            s_in[i] = v;
        }
        for (int i = tid; i < 8*512; i += 256) {
            int p = i >> 9;
            int r = i & 511;
            float w0 = w[(2*p    )*CIN*64 + ic0*64 + r];
            float w1 = w[(2*p + 1)*CIN*64 + ic0*64 + r];
            s_w2[i] = make_float2(w0, w1);
        }
        __syncthreads();

        for (int icl = 0; icl < 8; icl++) {
#pragma unroll
            for (int ky = 0; ky < 8; ky++) {
                const float* ip = &s_in[icl*600 + (row + ky)*40 + cs];
                float4 v0 = *(const float4*)(ip);
                float4 v1 = *(const float4*)(ip + 4);
                float4 v2 = *(const float4*)(ip + 8);
                float4 v3 = *(const float4*)(ip + 12);
                ull ivb[15];
                ivb[0]=bc2(v0.x); ivb[1]=bc2(v0.y); ivb[2]=bc2(v0.z); ivb[3]=bc2(v0.w);
                ivb[4]=bc2(v1.x); ivb[5]=bc2(v1.y); ivb[6]=bc2(v1.z); ivb[7]=bc2(v1.w);
                ivb[8]=bc2(v2.x); ivb[9]=bc2(v2.y); ivb[10]=bc2(v2.z); ivb[11]=bc2(v2.w);
                ivb[12]=bc2(v3.x); ivb[13]=bc2(v3.y); ivb[14]=bc2(v3.z);
                const float2* wrow = &s_w2[(pr*8 + icl)*64 + ky*8];
#pragma unroll
                for (int kx = 0; kx < 8; kx++) {
                    ull w2 = *(const ull*)&wrow[kx];
#pragma unroll
                    for (int j = 0; j < 8; j++)
                        ffma2(acc2[j], ivb[kx + j], w2);
                }
            }
        }
    }

    const int oy = y0 + row;
    if (oy < HOUT) {
        const int oc0 = 2*pr;
        const float b0 = bias[oc0], b1 = bias[oc0 + 1];
        float* o0 = &out[(((long)b*16 + oc0)*HOUT + oy)*WOUT];
        float* o1 = o0 + (long)HOUT*WOUT;
#pragma unroll
        for (int j = 0; j < 8; j++) {
            int ox = x0 + cs + j;
            if (ox < WOUT) {
                float2 f = up2(acc2[j]);
                o0[ox] = fmaxf(f.x + b0, 0.f);
                o1[ox] = fmaxf(f.y + b1, 0.f);
            }
        }
    }
}

// ===========================================================================
// conv4 (unchanged)
// ===========================================================================
__global__ void conv4_kernel(const float* __restrict__ in,
                             const float* __restrict__ w,
                             const float* __restrict__ bias,
                             float* __restrict__ out) {
    __shared__ float s_in[8*16*52];
    __shared__ float s_w[16*8*36];
    const int band = blockIdx.x;
    const int b = blockIdx.y;
    const int tid = threadIdx.x;
    const int ry0 = band * 6;

    float acc[9];
#pragma unroll
    for (int t = 0; t < 9; t++) acc[t] = 0.f;

    for (int chunk = 0; chunk < 2; chunk++) {
        const int ic0 = chunk * 8;
        __syncthreads();
        for (int i = tid; i < 8*16*52; i += 256) {
            int icl = i / (16*52);
            int r = (i / 52) % 16, c = i % 52;
            s_in[i] = in[(((long)b*16 + ic0 + icl)*52 + 12*band + r)*52 + c];
        }
        for (int i = tid; i < 16*8*36; i += 256) {
            int o = i / (8*36);
            int r = i % (8*36);
            int icl = r / 36, k = r % 36;
            s_w[i] = w[(o*16 + ic0 + icl)*36 + k];
        }
        __syncthreads();
#pragma unroll
        for (int t = 0; t < 9; t++) {
            int task = tid + t*256;
            if (task < 2304) {
                int oc = task / 144;
                int r = task % 144;
                int row = r / 24, cx = r % 24;
                float a = acc[t];
                for (int icl = 0; icl < 8; icl++) {
#pragma unroll
                    for (int ky = 0; ky < 6; ky++) {
                        const float* rp = &s_in[(icl*16 + 2*row + ky)*52 + 2*cx];
                        const float* wpp = &s_w[(oc*8 + icl)*36 + ky*6];
#pragma unroll
                        for (int kx = 0; kx < 6; kx++) a += rp[kx] * wpp[kx];
                    }
                }
                acc[t] = a;
            }
        }
    }
#pragma unroll
    for (int t = 0; t < 9; t++) {
        int task = tid + t*256;
        if (task < 2304) {
            int oc = task / 144;
            int r = task % 144;
            int row = r / 24, cx = r % 24;
            out[(((long)b*16 + oc)*24 + ry0 + row)*24 + cx] = fmaxf(acc[t] + bias[oc], 0.f);
        }
    }
}

// ===========================================================================
// conv5 (unchanged)
// ===========================================================================
__global__ void conv5_kernel(const float* __restrict__ in,
                             const float* __restrict__ w,
                             const float* __restrict__ bias,
                             float* __restrict__ out) {
    __shared__ float s_in[16*14*24];
    __shared__ float s_w[16*16*25];
    const int band = blockIdx.x;
    const int b = blockIdx.y;
    const int tid = threadIdx.x;
    const int ry0 = band * 10;

    for (int i = tid; i < 16*14*24; i += 256) {
        int icl = i / (14*24);
        int r = (i / 24) % 14, c = i % 24;
        s_in[i] = in[(((long)b*16 + icl)*24 + ry0 + r)*24 + c];
    }
    for (int i = tid; i < 16*16*25; i += 256)
        s_w[i] = w[i];
    __syncthreads();

#pragma unroll
    for (int t = 0; t < 13; t++) {
        int task = tid + t*256;
        if (task < 3200) {
            int oc = task / 200;
            int r = task % 200;
            int row = r / 20, cx = r % 20;
            float a = 0.f;
            for (int ic = 0; ic < 16; ic++) {
#pragma unroll
                for (int ky = 0; ky < 5; ky++) {
                    const float* rp = &s_in[(ic*14 + row + ky)*24 + cx];
                    const float* wpp = &s_w[(oc*16 + ic)*25 + ky*5];
#pragma unroll
                    for (int kx = 0; kx < 5; kx++) a += rp[kx] * wpp[kx];
                }
            }
            out[(((long)b*16 + oc)*20 + ry0 + row)*20 + cx] = fmaxf(a + bias[oc], 0.f);
        }
    }
}

// ===========================================================================
// GEMM for fc1/fc2 (unchanged)
// ===========================================================================
__global__ void __launch_bounds__(256)
gemm_relu_kernel(const float* __restrict__ X,
                 const float* __restrict__ W,
                 const float* __restrict__ bias,
                 float* __restrict__ out,
                 int N, int K) {
    __shared__ float xs[64][68];
    __shared__ float ws[64][68];
    const int n0 = blockIdx.x * 64;
    const int tid = threadIdx.x;
    const int tx = tid & 15, ty = tid >> 4;

    float acc[4][4];
#pragma unroll
    for (int i = 0; i < 4; i++)
#pragma unroll
        for (int j = 0; j < 4; j++) acc[i][j] = 0.f;

    for (int k0 = 0; k0 < K; k0 += 64) {
        __syncthreads();
        for (int i = tid; i < 64*64; i += 256) {
            int m = i >> 6, k = i & 63;
            xs[k][m] = X[m*K + k0 + k];
        }
        for (int i = tid; i < 64*64; i += 256) {
            int n = i >> 6, k = i & 63;
            ws[k][n] = W[(long)(n0 + n)*K + k0 + k];
        }
        __syncthreads();
#pragma unroll 8
        for (int k = 0; k < 64; k++) {
            float4 a4 = *(const float4*)&xs[k][ty*4];
            float4 b4 = *(const float4*)&ws[k][tx*4];
            float a[4] = {a4.x, a4.y, a4.z, a4.w};
            float bb[4] = {b4.x, b4.y, b4.z, b4.w};
#pragma unroll
            for (int i = 0; i < 4; i++)
#pragma unroll
                for (int j = 0; j < 4; j++)
                    acc[i][j] += a[i] * bb[j];
        }
    }
#pragma unroll
    for (int i = 0; i < 4; i++) {
        int m = ty*4 + i;
#pragma unroll
        for (int j = 0; j < 4; j++) {
            int n = n0 + tx*4 + j;
            out[m*N + n] = fmaxf(acc[i][j] + bias[n], 0.f);
        }
    }
}

// ===========================================================================
// fc3 (unchanged)
// ===========================================================================
__global__ void fc3_kernel(const float* __restrict__ X,
                           const float* __restrict__ W,
                           const float* __restrict__ bias,
                           float* __restrict__ out) {
    const int warp = (blockIdx.x * 256 + threadIdx.x) >> 5;
    const int lane = threadIdx.x & 31;
    if (warp >= 768) return;
    const int m = warp / 12, n = warp % 12;
    float s = 0.f;
    for (int k = lane; k < 2048; k += 32)
        s += X[m*2048 + k] * W[n*2048 + k];
#pragma unroll
    for (int o = 16; o; o >>= 1) s += __shfl_xor_sync(0xFFFFFFFFu, s, o);
    if (lane == 0) out[m*12 + n] = s + bias[n];
}

// ===========================================================================
extern "C" void kernel_launch(void* const* d_in, const int* in_sizes, int n_in,
                              void* d_out, int out_size) {
    const float* x       = (const float*)d_in[0];
    const float* conv1_w = (const float*)d_in[1];
    const float* conv1_b = (const float*)d_in[2];
    const float* rg_g    = (const float*)d_in[3];
    const float* rg_b    = (const float*)d_in[4];
    const float* rg_m    = (const float*)d_in[5];
    const float* rg_v    = (const float*)d_in[6];
    const float* rg_w    = (const float*)d_in[7];
    const float* rg_cb   = (const float*)d_in[8];
    const float* bn2_g   = (const float*)d_in[9];
    const float* bn2_b   = (const float*)d_in[10];
    const float* bn2_m   = (const float*)d_in[11];
    const float* bn2_v   = (const float*)d_in[12];
    const float* conv2_w = (const float*)d_in[13];
    const float* conv2_b = (const float*)d_in[14];
    const float* conv3_w = (const float*)d_in[15];
    const float* conv3_b = (const float*)d_in[16];
    const float* conv4_w = (const float*)d_in[17];
    const float* conv4_b = (const float*)d_in[18];
    const float* conv5_w = (const float*)d_in[19];
    const float* conv5_b = (const float*)d_in[20];
    const float* fc1_w   = (const float*)d_in[21];
    const float* fc1_b   = (const float*)d_in[22];
    const float* fc2_w   = (const float*)d_in[23];
    const float* fc2_b   = (const float*)d_in[24];
    const float* fc3_w   = (const float*)d_in[25];
    const float* fc3_b   = (const float*)d_in[26];

    float *b1, *b2, *b3, *b4, *b5, *b6, *f1, *f2;
    cudaGetSymbolAddress((void**)&b1, g_buf1);
    cudaGetSymbolAddress((void**)&b2, g_buf2);
    cudaGetSymbolAddress((void**)&b3, g_buf3);
    cudaGetSymbolAddress((void**)&b4, g_buf4);
    cudaGetSymbolAddress((void**)&b5, g_buf5);
    cudaGetSymbolAddress((void**)&b6, g_buf6);
    cudaGetSymbolAddress((void**)&f1, g_fc1o);
    cudaGetSymbolAddress((void**)&f2, g_fc2o);

    const int C1_SMEM = 49152 + 20448 + 1536;   // 71136 B
    cudaFuncSetAttribute(conv1_mma, cudaFuncAttributeMaxDynamicSharedMemorySize, C1_SMEM);

    conv1_bprep<<<48, 256>>>(conv1_w);
    conv1_mma<<<dim3(137, 64), 256, C1_SMEM>>>(x, conv1_b, b1);
    region_kernel<<<dim3(64, 64), 288>>>(b1, rg_g, rg_b, rg_m, rg_v, rg_w, rg_cb,
                                         bn2_g, bn2_b, bn2_m, bn2_v, b2);
    conv8x8_relu_kernel<32, 66, 66, 59, 59><<<dim3(2, 8, 64), 256>>>(b2, conv2_w, conv2_b, b3);
    conv8x8_relu_kernel<16, 59, 59, 52, 52><<<dim3(2, 7, 64), 256>>>(b3, conv3_w, conv3_b, b4);
    conv4_kernel<<<dim3(4, 64), 256>>>(b4, conv4_w, conv4_b, b5);
    conv5_kernel<<<dim3(2, 64), 256>>>(b5, conv5_w, conv5_b, b6);
    gemm_relu_kernel<<<64, 256>>>(b6, fc1_w, fc1_b, f1, 4096, 6400);
    gemm_relu_kernel<<<32, 256>>>(f1, fc2_w, fc2_b, f2, 2048, 4096);
    fc3_kernel<<<96, 256>>>(f2, fc3_w, fc3_b, (float*)d_out);
}